// round 4
// baseline (speedup 1.0000x reference)
#include <cuda_runtime.h>
#include <cuda_fp16.h>
#include <cstdint>

// Problem dims
#define BROWS 8192
#define DIN   2048
#define DOUT  2048

// GEMM tiling (sm_100-base-target safe: mma.sync + ldmatrix + cp.async only)
#define BM 128
#define BN 256
#define BK 32
#define NSTAGES 4
#define NITER   (DIN / BK)          // 64

#define ROW_HALVES (BK + 8)         // 40 halves -> 80B row stride (conflict-free ldmatrix)
#define ROW_BYTES  (ROW_HALVES * 2) // 80
#define A_STAGE_BYTES (BM * ROW_BYTES)              // 10240
#define B_STAGE_BYTES (BN * ROW_BYTES)              // 20480
#define STAGE_BYTES   (A_STAGE_BYTES + B_STAGE_BYTES) // 30720
#define SMEM_BYTES    (NSTAGES * STAGE_BYTES)       // 122880

// Scratch (device globals: allocation-free)
__device__ __half g_A[(size_t)BROWS * DIN];   // 32 MB fp16 input, row-major [M,K]
__device__ __half g_B[(size_t)DOUT * DIN];    // 8 MB binarized weights, [N,K] (K-major)

// ---------------------------------------------------------------------------
// helpers
// ---------------------------------------------------------------------------
__device__ __forceinline__ uint32_t smem_u32(const void* p) {
    uint32_t a;
    asm("{ .reg .u64 t; cvta.to.shared.u64 t, %1; cvt.u32.u64 %0, t; }" : "=r"(a) : "l"(p));
    return a;
}

__device__ __forceinline__ void cp_async16(uint32_t dst, const void* src) {
    asm volatile("cp.async.cg.shared.global [%0], [%1], 16;\n" :: "r"(dst), "l"(src));
}

__device__ __forceinline__ void ldsm_x4(uint32_t& r0, uint32_t& r1, uint32_t& r2, uint32_t& r3,
                                        uint32_t addr) {
    asm volatile("ldmatrix.sync.aligned.m8n8.x4.shared.b16 {%0,%1,%2,%3}, [%4];"
                 : "=r"(r0), "=r"(r1), "=r"(r2), "=r"(r3) : "r"(addr));
}

__device__ __forceinline__ void mma16816(float* c, const uint32_t* a, const uint32_t* b) {
    asm volatile(
        "mma.sync.aligned.m16n8k16.row.col.f32.f16.f16.f32 "
        "{%0,%1,%2,%3}, {%4,%5,%6,%7}, {%8,%9}, {%0,%1,%2,%3};"
        : "+f"(c[0]), "+f"(c[1]), "+f"(c[2]), "+f"(c[3])
        : "r"(a[0]), "r"(a[1]), "r"(a[2]), "r"(a[3]), "r"(b[0]), "r"(b[1]));
}

// ---------------------------------------------------------------------------
// Prologue kernel 1: fp32 -> fp16 input copy (row-major [M,K])
// ---------------------------------------------------------------------------
__global__ void __launch_bounds__(256) convert_input_kernel(const float* __restrict__ x) {
    int i = blockIdx.x * blockDim.x + threadIdx.x;   // float4 index
    const int n4 = (BROWS * DIN) / 4;
    if (i >= n4) return;
    float4 v = reinterpret_cast<const float4*>(x)[i];
    __half2* o = reinterpret_cast<__half2*>(g_A);
    o[2 * i]     = __floats2half2_rn(v.x, v.y);
    o[2 * i + 1] = __floats2half2_rn(v.z, v.w);
}

// ---------------------------------------------------------------------------
// Prologue kernel 2: binarize w[k][n] -> g_B[n][k] fp16 (transpose, {0,1})
// ---------------------------------------------------------------------------
__global__ void __launch_bounds__(256) binarize_transpose_kernel(const float* __restrict__ w) {
    __shared__ __half tile[32][33];
    int n0 = blockIdx.x * 32;
    int k0 = blockIdx.y * 32;
    int tx = threadIdx.x;   // 0..31
    int ty = threadIdx.y;   // 0..7
    #pragma unroll
    for (int j = 0; j < 32; j += 8) {
        float v = w[(size_t)(k0 + ty + j) * DOUT + (n0 + tx)];
        tile[ty + j][tx] = __float2half(v < 0.0f ? 0.0f : 1.0f);
    }
    __syncthreads();
    #pragma unroll
    for (int j = 0; j < 32; j += 8) {
        g_B[(size_t)(n0 + ty + j) * DIN + (k0 + tx)] = tile[tx][ty + j];
    }
}

// ---------------------------------------------------------------------------
// GEMM: out[8192,2048] = g_A @ g_B^T   (g_B stored [N,K])
// CTA 128x256x32, 512 threads, 16 warps (4M x 4N), warp tile 32x64.
// 4-stage cp.async pipeline; mma.sync.m16n8k16 fp16 -> fp32.
// ---------------------------------------------------------------------------
__device__ __forceinline__ void fill_stage(uint32_t stage_base, int iter,
                                           const __half* __restrict__ Ab,
                                           const __half* __restrict__ Bb, int tid) {
    uint32_t sA = stage_base;
    uint32_t sB = stage_base + A_STAGE_BYTES;
    const __half* a = Ab + iter * BK;
    const __half* b = Bb + iter * BK;
    // A: 128 rows x 4 chunks (16B) = 512 -> one per thread
    {
        int row = tid >> 2, ch = tid & 3;
        cp_async16(sA + row * ROW_BYTES + ch * 16, a + (size_t)row * DIN + ch * 8);
    }
    // B: 256 rows x 4 chunks = 1024 -> two per thread
    #pragma unroll
    for (int i = 0; i < 2; i++) {
        int idx = tid + i * 512;
        int row = idx >> 2, ch = idx & 3;
        cp_async16(sB + row * ROW_BYTES + ch * 16, b + (size_t)row * DIN + ch * 8);
    }
}

__global__ void __launch_bounds__(512, 1)
binary_dense_gemm_kernel(float* __restrict__ out) {
    extern __shared__ char smem[];
    uint32_t sbase = smem_u32(smem);

    int tid   = threadIdx.x;
    int lane  = tid & 31;
    int wid   = tid >> 5;          // 0..15
    int warpM = wid & 3;           // 4 M-warps
    int warpN = wid >> 2;          // 4 N-warps
    int lr    = lane & 7;          // ldmatrix row within group
    int lg    = lane >> 3;         // ldmatrix group 0..3

    const __half* Ab = g_A + (size_t)blockIdx.y * BM * DIN;
    const __half* Bb = g_B + (size_t)blockIdx.x * BN * DIN;

    float acc[2][8][4];
    #pragma unroll
    for (int i = 0; i < 2; i++)
        #pragma unroll
        for (int j = 0; j < 8; j++)
            #pragma unroll
            for (int c = 0; c < 4; c++) acc[i][j][c] = 0.0f;

    // prologue: fill stages 0..NSTAGES-2
    #pragma unroll
    for (int s = 0; s < NSTAGES - 1; s++) {
        fill_stage(sbase + s * STAGE_BYTES, s, Ab, Bb, tid);
        asm volatile("cp.async.commit_group;\n" ::: "memory");
    }

    for (int kk = 0; kk < NITER; kk++) {
        asm volatile("cp.async.wait_group %0;\n" :: "n"(NSTAGES - 2) : "memory");
        __syncthreads();

        // refill (or empty-commit to keep group count uniform)
        int j = kk + NSTAGES - 1;
        if (j < NITER)
            fill_stage(sbase + (j % NSTAGES) * STAGE_BYTES, j, Ab, Bb, tid);
        asm volatile("cp.async.commit_group;\n" ::: "memory");

        // compute on stage kk
        uint32_t stage = sbase + (kk % NSTAGES) * STAGE_BYTES;
        uint32_t sA = stage;
        uint32_t sB = stage + A_STAGE_BYTES;

        #pragma unroll
        for (int ks = 0; ks < 2; ks++) {
            int k0 = ks * 16;
            // A fragments: 2 m-tiles of 16x16
            uint32_t af[2][4];
            #pragma unroll
            for (int i = 0; i < 2; i++) {
                int m = warpM * 32 + i * 16 + (lg & 1) * 8 + lr;
                int k = k0 + (lg >> 1) * 8;
                ldsm_x4(af[i][0], af[i][1], af[i][2], af[i][3],
                        sA + m * ROW_BYTES + k * 2);
            }
            // B fragments: 8 n-tiles of 16(k)x8(n), loaded 2 at a time
            uint32_t bf[8][2];
            #pragma unroll
            for (int jp = 0; jp < 4; jp++) {
                int n = warpN * 64 + jp * 16 + (lg >> 1) * 8 + lr;
                int k = k0 + (lg & 1) * 8;
                uint32_t r0, r1, r2, r3;
                ldsm_x4(r0, r1, r2, r3, sB + n * ROW_BYTES + k * 2);
                bf[2 * jp][0] = r0; bf[2 * jp][1] = r1;
                bf[2 * jp + 1][0] = r2; bf[2 * jp + 1][1] = r3;
            }
            #pragma unroll
            for (int i = 0; i < 2; i++)
                #pragma unroll
                for (int jn = 0; jn < 8; jn++)
                    mma16816(acc[i][jn], af[i], bf[jn]);
        }
    }

    // epilogue: direct float2 stores (fragment layout)
    int mb = blockIdx.y * BM + warpM * 32;
    int nb = blockIdx.x * BN + warpN * 64;
    int mrow = mb + (lane >> 2);
    int ncol = nb + (lane & 3) * 2;
    #pragma unroll
    for (int i = 0; i < 2; i++) {
        #pragma unroll
        for (int jn = 0; jn < 8; jn++) {
            float* p0 = out + (size_t)(mrow + i * 16) * DOUT + ncol + jn * 8;
            float* p1 = p0 + 8 * DOUT;
            *reinterpret_cast<float2*>(p0) = make_float2(acc[i][jn][0], acc[i][jn][1]);
            *reinterpret_cast<float2*>(p1) = make_float2(acc[i][jn][2], acc[i][jn][3]);
        }
    }
}

// ---------------------------------------------------------------------------
// launch
// ---------------------------------------------------------------------------
extern "C" void kernel_launch(void* const* d_in, const int* in_sizes, int n_in,
                              void* d_out, int out_size) {
    const float* x = (const float*)d_in[0];   // input_tensor [8192, 2048]
    const float* w = (const float*)d_in[1];   // w [2048, 2048]
    float* out = (float*)d_out;

    cudaFuncSetAttribute(binary_dense_gemm_kernel,
                         cudaFuncAttributeMaxDynamicSharedMemorySize, SMEM_BYTES);

    {
        const int n4 = (BROWS * DIN) / 4;
        convert_input_kernel<<<(n4 + 255) / 256, 256>>>(x);
    }
    binarize_transpose_kernel<<<dim3(DOUT / 32, DIN / 32), dim3(32, 8)>>>(w);
    binary_dense_gemm_kernel<<<dim3(DOUT / BN, BROWS / BM), 512, SMEM_BYTES>>>(out);
}

// round 5
// speedup vs baseline: 1.0450x; 1.0450x over previous
#include <cuda_runtime.h>
#include <cuda_fp16.h>
#include <cstdint>

// Problem dims
#define BROWS 8192
#define DIN   2048
#define DOUT  2048

// GEMM tiling (sm_100-base-target safe: mma.sync + ldmatrix + cp.async only)
#define BM 128
#define BN 256
#define BK 64
#define NSTAGES 3
#define NITER   (DIN / BK)          // 32

#define ROW_HALVES (BK + 8)         // 72 halves -> 144B row stride (conflict-free ldmatrix)
#define ROW_BYTES  (ROW_HALVES * 2) // 144
#define A_STAGE_BYTES (BM * ROW_BYTES)                // 18432
#define B_STAGE_BYTES (BN * ROW_BYTES)                // 36864
#define STAGE_BYTES   (A_STAGE_BYTES + B_STAGE_BYTES) // 55296
#define SMEM_BYTES    (NSTAGES * STAGE_BYTES)         // 165888

// Scratch (device globals: allocation-free)
__device__ __half g_A[(size_t)BROWS * DIN];   // 32 MB fp16 input, row-major [M,K]
__device__ __half g_B[(size_t)DOUT * DIN];    // 8 MB binarized weights, [N,K] (K-major)

// ---------------------------------------------------------------------------
// helpers
// ---------------------------------------------------------------------------
__device__ __forceinline__ uint32_t smem_u32(const void* p) {
    uint32_t a;
    asm("{ .reg .u64 t; cvta.to.shared.u64 t, %1; cvt.u32.u64 %0, t; }" : "=r"(a) : "l"(p));
    return a;
}

__device__ __forceinline__ void cp_async16(uint32_t dst, const void* src) {
    asm volatile("cp.async.cg.shared.global [%0], [%1], 16;\n" :: "r"(dst), "l"(src));
}

__device__ __forceinline__ void ldsm_x4(uint32_t& r0, uint32_t& r1, uint32_t& r2, uint32_t& r3,
                                        uint32_t addr) {
    asm volatile("ldmatrix.sync.aligned.m8n8.x4.shared.b16 {%0,%1,%2,%3}, [%4];"
                 : "=r"(r0), "=r"(r1), "=r"(r2), "=r"(r3) : "r"(addr));
}

__device__ __forceinline__ void mma16816(float* c, const uint32_t* a, const uint32_t* b) {
    asm volatile(
        "mma.sync.aligned.m16n8k16.row.col.f32.f16.f16.f32 "
        "{%0,%1,%2,%3}, {%4,%5,%6,%7}, {%8,%9}, {%0,%1,%2,%3};"
        : "+f"(c[0]), "+f"(c[1]), "+f"(c[2]), "+f"(c[3])
        : "r"(a[0]), "r"(a[1]), "r"(a[2]), "r"(a[3]), "r"(b[0]), "r"(b[1]));
}

// ---------------------------------------------------------------------------
// Prologue kernel 1: fp32 -> fp16 input copy (row-major [M,K])
// ---------------------------------------------------------------------------
__global__ void __launch_bounds__(256) convert_input_kernel(const float* __restrict__ x) {
    int i = blockIdx.x * blockDim.x + threadIdx.x;   // float4 index
    const int n4 = (BROWS * DIN) / 4;
    if (i >= n4) return;
    float4 v = reinterpret_cast<const float4*>(x)[i];
    __half2* o = reinterpret_cast<__half2*>(g_A);
    o[2 * i]     = __floats2half2_rn(v.x, v.y);
    o[2 * i + 1] = __floats2half2_rn(v.z, v.w);
}

// ---------------------------------------------------------------------------
// Prologue kernel 2: binarize w[k][n] -> g_B[n][k] fp16 (transpose, {0,1})
// ---------------------------------------------------------------------------
__global__ void __launch_bounds__(256) binarize_transpose_kernel(const float* __restrict__ w) {
    __shared__ __half tile[32][33];
    int n0 = blockIdx.x * 32;
    int k0 = blockIdx.y * 32;
    int tx = threadIdx.x;   // 0..31
    int ty = threadIdx.y;   // 0..7
    #pragma unroll
    for (int j = 0; j < 32; j += 8) {
        float v = w[(size_t)(k0 + ty + j) * DOUT + (n0 + tx)];
        tile[ty + j][tx] = __float2half(v < 0.0f ? 0.0f : 1.0f);
    }
    __syncthreads();
    #pragma unroll
    for (int j = 0; j < 32; j += 8) {
        g_B[(size_t)(n0 + ty + j) * DIN + (k0 + tx)] = tile[tx][ty + j];
    }
}

// ---------------------------------------------------------------------------
// GEMM: out[8192,2048] = g_A @ g_B^T   (g_B stored [N,K])
// CTA 128x256x64, 256 threads, 8 warps (2M x 4N), warp tile 64x64.
// 3-stage cp.async pipeline; mma.sync.m16n8k16 fp16 -> fp32.
// Fragment double-buffer across the 4 k-substeps.
// ---------------------------------------------------------------------------
__device__ __forceinline__ void fill_stage(uint32_t stage_base, int iter,
                                           const __half* __restrict__ Ab,
                                           const __half* __restrict__ Bb, int tid) {
    uint32_t sA = stage_base;
    uint32_t sB = stage_base + A_STAGE_BYTES;
    const __half* a = Ab + iter * BK;
    const __half* b = Bb + iter * BK;
    // A: 128 rows x 8 chunks (16B) = 1024 -> 4 per thread
    #pragma unroll
    for (int i = 0; i < 4; i++) {
        int idx = tid + i * 256;
        int row = idx >> 3, ch = idx & 7;
        cp_async16(sA + row * ROW_BYTES + ch * 16, a + (size_t)row * DIN + ch * 8);
    }
    // B: 256 rows x 8 chunks = 2048 -> 8 per thread
    #pragma unroll
    for (int i = 0; i < 8; i++) {
        int idx = tid + i * 256;
        int row = idx >> 3, ch = idx & 7;
        cp_async16(sB + row * ROW_BYTES + ch * 16, b + (size_t)row * DIN + ch * 8);
    }
}

__device__ __forceinline__ void load_frags(uint32_t sA, uint32_t sB, int ks,
                                           int warpM, int warpN, int lr, int lg,
                                           uint32_t af[4][4], uint32_t bf[8][2]) {
    int ka = ks * 16 + (lg >> 1) * 8;
    int kb = ks * 16 + (lg & 1) * 8;
    #pragma unroll
    for (int i = 0; i < 4; i++) {
        int m = warpM * 64 + i * 16 + (lg & 1) * 8 + lr;
        ldsm_x4(af[i][0], af[i][1], af[i][2], af[i][3], sA + m * ROW_BYTES + ka * 2);
    }
    #pragma unroll
    for (int jp = 0; jp < 4; jp++) {
        int n = warpN * 64 + jp * 16 + (lg >> 1) * 8 + lr;
        uint32_t r0, r1, r2, r3;
        ldsm_x4(r0, r1, r2, r3, sB + n * ROW_BYTES + kb * 2);
        bf[2 * jp][0] = r0;     bf[2 * jp][1] = r1;
        bf[2 * jp + 1][0] = r2; bf[2 * jp + 1][1] = r3;
    }
}

__global__ void __launch_bounds__(256, 1)
binary_dense_gemm_kernel(float* __restrict__ out) {
    extern __shared__ char smem[];
    uint32_t sbase = smem_u32(smem);

    int tid   = threadIdx.x;
    int lane  = tid & 31;
    int wid   = tid >> 5;          // 0..7
    int warpM = wid & 1;           // 2 M-warps
    int warpN = wid >> 1;          // 4 N-warps
    int lr    = lane & 7;
    int lg    = lane >> 3;

    const __half* Ab = g_A + (size_t)blockIdx.y * BM * DIN;
    const __half* Bb = g_B + (size_t)blockIdx.x * BN * DIN;

    float acc[4][8][4];
    #pragma unroll
    for (int i = 0; i < 4; i++)
        #pragma unroll
        for (int j = 0; j < 8; j++)
            #pragma unroll
            for (int c = 0; c < 4; c++) acc[i][j][c] = 0.0f;

    // prologue: fill stages 0..NSTAGES-2
    #pragma unroll
    for (int s = 0; s < NSTAGES - 1; s++) {
        fill_stage(sbase + s * STAGE_BYTES, s, Ab, Bb, tid);
        asm volatile("cp.async.commit_group;\n" ::: "memory");
    }

    uint32_t af[2][4][4];
    uint32_t bf[2][8][2];

    for (int kk = 0; kk < NITER; kk++) {
        asm volatile("cp.async.wait_group %0;\n" :: "n"(NSTAGES - 2) : "memory");
        __syncthreads();

        // refill (or empty-commit to keep group count uniform)
        int j = kk + NSTAGES - 1;
        if (j < NITER)
            fill_stage(sbase + (j % NSTAGES) * STAGE_BYTES, j, Ab, Bb, tid);
        asm volatile("cp.async.commit_group;\n" ::: "memory");

        // compute on stage kk: 4 k-substeps, fragment double-buffered
        uint32_t stage = sbase + (kk % NSTAGES) * STAGE_BYTES;
        uint32_t sA = stage;
        uint32_t sB = stage + A_STAGE_BYTES;

        load_frags(sA, sB, 0, warpM, warpN, lr, lg, af[0], bf[0]);
        #pragma unroll
        for (int ks = 0; ks < 4; ks++) {
            int cur = ks & 1;
            if (ks < 3)
                load_frags(sA, sB, ks + 1, warpM, warpN, lr, lg, af[cur ^ 1], bf[cur ^ 1]);
            #pragma unroll
            for (int i = 0; i < 4; i++)
                #pragma unroll
                for (int jn = 0; jn < 8; jn++)
                    mma16816(acc[i][jn], af[cur][i], bf[cur][jn]);
        }
    }

    // epilogue: direct float2 stores (fragment layout)
    int mb = blockIdx.y * BM + warpM * 64;
    int nb = blockIdx.x * BN + warpN * 64;
    int mrow = mb + (lane >> 2);
    int ncol = nb + (lane & 3) * 2;
    #pragma unroll
    for (int i = 0; i < 4; i++) {
        #pragma unroll
        for (int jn = 0; jn < 8; jn++) {
            float* p0 = out + (size_t)(mrow + i * 16) * DOUT + ncol + jn * 8;
            float* p1 = p0 + 8 * DOUT;
            *reinterpret_cast<float2*>(p0) = make_float2(acc[i][jn][0], acc[i][jn][1]);
            *reinterpret_cast<float2*>(p1) = make_float2(acc[i][jn][2], acc[i][jn][3]);
        }
    }
}

// ---------------------------------------------------------------------------
// launch
// ---------------------------------------------------------------------------
extern "C" void kernel_launch(void* const* d_in, const int* in_sizes, int n_in,
                              void* d_out, int out_size) {
    const float* x = (const float*)d_in[0];   // input_tensor [8192, 2048]
    const float* w = (const float*)d_in[1];   // w [2048, 2048]
    float* out = (float*)d_out;

    cudaFuncSetAttribute(binary_dense_gemm_kernel,
                         cudaFuncAttributeMaxDynamicSharedMemorySize, SMEM_BYTES);

    {
        const int n4 = (BROWS * DIN) / 4;
        convert_input_kernel<<<(n4 + 255) / 256, 256>>>(x);
    }
    binarize_transpose_kernel<<<dim3(DOUT / 32, DIN / 32), dim3(32, 8)>>>(w);
    binary_dense_gemm_kernel<<<dim3(DOUT / BN, BROWS / BM), 256, SMEM_BYTES>>>(out);
}

// round 7
// speedup vs baseline: 1.2307x; 1.1778x over previous
#include <cuda_runtime.h>
#include <cuda_fp16.h>
#include <cstdint>

// Problem dims
#define BROWS 8192
#define DIN   2048
#define DOUT  2048

// GEMM tiling (sm_100-base-target safe: mma.sync + ldmatrix + cp.async only)
#define BM 128
#define BN 128
#define BK 32
#define NSTAGES 4
#define NITER   (DIN / BK)          // 64

#define ROW_HALVES (BK + 8)         // 40 halves -> 80B row stride (conflict-free ldmatrix)
#define ROW_BYTES  (ROW_HALVES * 2) // 80
#define A_STAGE_BYTES (BM * ROW_BYTES)                // 10240
#define B_STAGE_BYTES (BN * ROW_BYTES)                // 10240
#define STAGE_BYTES   (A_STAGE_BYTES + B_STAGE_BYTES) // 20480
#define SMEM_BYTES    (NSTAGES * STAGE_BYTES)         // 81920  (x2 CTAs/SM = 160KB)

// Scratch (device globals: allocation-free)
__device__ __half g_A[(size_t)BROWS * DIN];   // 32 MB fp16 input, row-major [M,K]
__device__ __half g_B[(size_t)DOUT * DIN];    // 8 MB binarized weights, [N,K] (K-major)

// ---------------------------------------------------------------------------
// helpers
// ---------------------------------------------------------------------------
__device__ __forceinline__ uint32_t smem_u32(const void* p) {
    uint32_t a;
    asm("{ .reg .u64 t; cvta.to.shared.u64 t, %1; cvt.u32.u64 %0, t; }" : "=r"(a) : "l"(p));
    return a;
}

__device__ __forceinline__ void cp_async16(uint32_t dst, const void* src) {
    asm volatile("cp.async.cg.shared.global [%0], [%1], 16;\n" :: "r"(dst), "l"(src));
}

__device__ __forceinline__ void ldsm_x4(uint32_t& r0, uint32_t& r1, uint32_t& r2, uint32_t& r3,
                                        uint32_t addr) {
    asm volatile("ldmatrix.sync.aligned.m8n8.x4.shared.b16 {%0,%1,%2,%3}, [%4];"
                 : "=r"(r0), "=r"(r1), "=r"(r2), "=r"(r3) : "r"(addr));
}

__device__ __forceinline__ void mma16816(float* c, const uint32_t* a, const uint32_t* b) {
    asm volatile(
        "mma.sync.aligned.m16n8k16.row.col.f32.f16.f16.f32 "
        "{%0,%1,%2,%3}, {%4,%5,%6,%7}, {%8,%9}, {%0,%1,%2,%3};"
        : "+f"(c[0]), "+f"(c[1]), "+f"(c[2]), "+f"(c[3])
        : "r"(a[0]), "r"(a[1]), "r"(a[2]), "r"(a[3]), "r"(b[0]), "r"(b[1]));
}

// ---------------------------------------------------------------------------
// Prologue kernel 1: fp32 -> fp16 input copy (row-major [M,K])
// Two independent float4s per thread for MLP.
// ---------------------------------------------------------------------------
__global__ void __launch_bounds__(256) convert_input_kernel(const float* __restrict__ x) {
    const int n4 = (BROWS * DIN) / 4;        // 4M float4s
    const int half = n4 / 2;
    int i = blockIdx.x * blockDim.x + threadIdx.x;
    if (i >= half) return;
    float4 v0 = reinterpret_cast<const float4*>(x)[i];
    float4 v1 = reinterpret_cast<const float4*>(x)[i + half];
    __half2* o = reinterpret_cast<__half2*>(g_A);
    o[2 * i]              = __floats2half2_rn(v0.x, v0.y);
    o[2 * i + 1]          = __floats2half2_rn(v0.z, v0.w);
    o[2 * (i + half)]     = __floats2half2_rn(v1.x, v1.y);
    o[2 * (i + half) + 1] = __floats2half2_rn(v1.z, v1.w);
}

// ---------------------------------------------------------------------------
// Prologue kernel 2: binarize w[k][n] -> g_B[n][k] fp16 (transpose, {0,1})
// ---------------------------------------------------------------------------
__global__ void __launch_bounds__(256) binarize_transpose_kernel(const float* __restrict__ w) {
    __shared__ __half tile[32][33];
    int n0 = blockIdx.x * 32;
    int k0 = blockIdx.y * 32;
    int tx = threadIdx.x;   // 0..31
    int ty = threadIdx.y;   // 0..7
    #pragma unroll
    for (int j = 0; j < 32; j += 8) {
        float v = w[(size_t)(k0 + ty + j) * DOUT + (n0 + tx)];
        tile[ty + j][tx] = __float2half(v < 0.0f ? 0.0f : 1.0f);
    }
    __syncthreads();
    #pragma unroll
    for (int j = 0; j < 32; j += 8) {
        g_B[(size_t)(n0 + ty + j) * DIN + (k0 + tx)] = tile[tx][ty + j];
    }
}

// ---------------------------------------------------------------------------
// GEMM: out[8192,2048] = g_A @ g_B^T   (g_B stored [N,K])
// CTA 128x128x32, 128 threads, 4 warps (2M x 2N), warp tile 64x64.
// 4-stage cp.async pipeline, 2 CTAs/SM; mma.sync.m16n8k16 fp16 -> fp32.
// ---------------------------------------------------------------------------
__device__ __forceinline__ void fill_stage(uint32_t stage_base, int iter,
                                           const __half* __restrict__ Ab,
                                           const __half* __restrict__ Bb, int tid) {
    uint32_t sA = stage_base;
    uint32_t sB = stage_base + A_STAGE_BYTES;
    const __half* a = Ab + iter * BK;
    const __half* b = Bb + iter * BK;
    // A: 128 rows x 4 chunks (16B) = 512 -> 4 per thread
    #pragma unroll
    for (int i = 0; i < 4; i++) {
        int idx = tid + i * 128;
        int row = idx >> 2, ch = idx & 3;
        cp_async16(sA + row * ROW_BYTES + ch * 16, a + (size_t)row * DIN + ch * 8);
    }
    // B: 128 rows x 4 chunks = 512 -> 4 per thread
    #pragma unroll
    for (int i = 0; i < 4; i++) {
        int idx = tid + i * 128;
        int row = idx >> 2, ch = idx & 3;
        cp_async16(sB + row * ROW_BYTES + ch * 16, b + (size_t)row * DIN + ch * 8);
    }
}

__device__ __forceinline__ void load_frags(uint32_t sA, uint32_t sB, int ks,
                                           int warpM, int warpN, int lr, int lg,
                                           uint32_t af[4][4], uint32_t bf[8][2]) {
    int ka = ks * 16 + (lg >> 1) * 8;
    int kb = ks * 16 + (lg & 1) * 8;
    #pragma unroll
    for (int i = 0; i < 4; i++) {
        int m = warpM * 64 + i * 16 + (lg & 1) * 8 + lr;
        ldsm_x4(af[i][0], af[i][1], af[i][2], af[i][3], sA + m * ROW_BYTES + ka * 2);
    }
    #pragma unroll
    for (int jp = 0; jp < 4; jp++) {
        int n = warpN * 64 + jp * 16 + (lg >> 1) * 8 + lr;
        uint32_t r0, r1, r2, r3;
        ldsm_x4(r0, r1, r2, r3, sB + n * ROW_BYTES + kb * 2);
        bf[2 * jp][0] = r0;     bf[2 * jp][1] = r1;
        bf[2 * jp + 1][0] = r2; bf[2 * jp + 1][1] = r3;
    }
}

__global__ void __launch_bounds__(128, 2)
binary_dense_gemm_kernel(float* __restrict__ out) {
    extern __shared__ char smem[];
    uint32_t sbase = smem_u32(smem);

    int tid   = threadIdx.x;
    int lane  = tid & 31;
    int wid   = tid >> 5;          // 0..3
    int warpM = wid & 1;           // 2 M-warps
    int warpN = wid >> 1;          // 2 N-warps
    int lr    = lane & 7;
    int lg    = lane >> 3;

    const __half* Ab = g_A + (size_t)blockIdx.y * BM * DIN;
    const __half* Bb = g_B + (size_t)blockIdx.x * BN * DIN;

    float acc[4][8][4];
    #pragma unroll
    for (int i = 0; i < 4; i++)
        #pragma unroll
        for (int j = 0; j < 8; j++)
            #pragma unroll
            for (int c = 0; c < 4; c++) acc[i][j][c] = 0.0f;

    // prologue: fill stages 0..NSTAGES-2
    #pragma unroll
    for (int s = 0; s < NSTAGES - 1; s++) {
        fill_stage(sbase + s * STAGE_BYTES, s, Ab, Bb, tid);
        asm volatile("cp.async.commit_group;\n" ::: "memory");
    }

    uint32_t af[2][4][4];
    uint32_t bf[2][8][2];

    for (int kk = 0; kk < NITER; kk++) {
        asm volatile("cp.async.wait_group %0;\n" :: "n"(NSTAGES - 2) : "memory");
        __syncthreads();

        // refill (or empty-commit to keep group count uniform)
        int j = kk + NSTAGES - 1;
        if (j < NITER)
            fill_stage(sbase + (j % NSTAGES) * STAGE_BYTES, j, Ab, Bb, tid);
        asm volatile("cp.async.commit_group;\n" ::: "memory");

        // compute on stage kk: 2 k-substeps, fragment double-buffered
        uint32_t stage = sbase + (kk % NSTAGES) * STAGE_BYTES;
        uint32_t sA = stage;
        uint32_t sB = stage + A_STAGE_BYTES;

        load_frags(sA, sB, 0, warpM, warpN, lr, lg, af[0], bf[0]);
        #pragma unroll
        for (int ks = 0; ks < 2; ks++) {
            int cur = ks & 1;
            if (ks < 1)
                load_frags(sA, sB, ks + 1, warpM, warpN, lr, lg, af[cur ^ 1], bf[cur ^ 1]);
            #pragma unroll
            for (int i = 0; i < 4; i++)
                #pragma unroll
                for (int jn = 0; jn < 8; jn++)
                    mma16816(acc[i][jn], af[cur][i], bf[cur][jn]);
        }
    }

    // epilogue: direct float2 stores (fragment layout)
    int mb = blockIdx.y * BM + warpM * 64;
    int nb = blockIdx.x * BN + warpN * 64;
    int mrow = mb + (lane >> 2);
    int ncol = nb + (lane & 3) * 2;
    #pragma unroll
    for (int i = 0; i < 4; i++) {
        #pragma unroll
        for (int jn = 0; jn < 8; jn++) {
            float* p0 = out + (size_t)(mrow + i * 16) * DOUT + ncol + jn * 8;
            float* p1 = p0 + 8 * DOUT;
            *reinterpret_cast<float2*>(p0) = make_float2(acc[i][jn][0], acc[i][jn][1]);
            *reinterpret_cast<float2*>(p1) = make_float2(acc[i][jn][2], acc[i][jn][3]);
        }
    }
}

// ---------------------------------------------------------------------------
// launch
// ---------------------------------------------------------------------------
extern "C" void kernel_launch(void* const* d_in, const int* in_sizes, int n_in,
                              void* d_out, int out_size) {
    const float* x = (const float*)d_in[0];   // input_tensor [8192, 2048]
    const float* w = (const float*)d_in[1];   // w [2048, 2048]
    float* out = (float*)d_out;

    cudaFuncSetAttribute(binary_dense_gemm_kernel,
                         cudaFuncAttributeMaxDynamicSharedMemorySize, SMEM_BYTES);

    {
        const int n8 = (BROWS * DIN) / 8;   // threads (2 float4s each)
        convert_input_kernel<<<(n8 + 255) / 256, 256>>>(x);
    }
    binarize_transpose_kernel<<<dim3(DOUT / 32, DIN / 32), dim3(32, 8)>>>(w);
    binary_dense_gemm_kernel<<<dim3(DOUT / BN, BROWS / BM), 128, SMEM_BYTES>>>(out);
}